// round 1
// baseline (speedup 1.0000x reference)
#include <cuda_runtime.h>
#include <cuda_bf16.h>
#include <math.h>

#define BB 2
#define TT 2048
#define CC 768
#define HH 12
#define DD 64
#define NLEFT 6
#define NQKV (3 * CC)   // 2304
#define MM (BB * TT)    // 4096

// Scratch: qkv in [which][B][H][T][D] layout, ctx in [B][T][C]
__device__ float g_qkv[3ull * BB * HH * TT * DD];
__device__ float g_ctx[(size_t)BB * TT * CC];

// ---------------------------------------------------------------------------
// SGEMM NT: C[m,n] = sum_k A[m,k] * Bw[n,k] + bias[n]
// A: [M,K] row-major, Bw: [N,K] row-major. Tiles 128x128x16, 256 thr, 8x8.
// ---------------------------------------------------------------------------
#define GBM 128
#define GBN 128
#define GBK 16

// Epilogue mode 0: plain store to Cout[m*N+n]
// Epilogue mode 1: scatter into g_qkv ([which][B][H][T][D])
template <int MODE>
__global__ __launch_bounds__(256)
void sgemm_nt_kernel(const float* __restrict__ A,
                     const float* __restrict__ Bw,
                     const float* __restrict__ bias,
                     float* __restrict__ Cout,
                     int M, int N, int K)
{
    __shared__ float As[GBK][GBM];
    __shared__ float Bs[GBK][GBN];

    const int bm = blockIdx.y * GBM;
    const int bn = blockIdx.x * GBN;
    const int tid = threadIdx.x;
    const int ty = tid / 16;   // 0..15
    const int tx = tid % 16;   // 0..15

    float acc[8][8];
#pragma unroll
    for (int i = 0; i < 8; i++)
#pragma unroll
        for (int j = 0; j < 8; j++) acc[i][j] = 0.f;

    const int lrow = tid >> 2;        // 0..63
    const int lc4  = (tid & 3) * 4;   // 0,4,8,12

    for (int k0 = 0; k0 < K; k0 += GBK) {
        // load A tile (BMxBK) transposed into As[k][m]
#pragma unroll
        for (int rr = 0; rr < GBM; rr += 64) {
            float4 v = *(const float4*)&A[(size_t)(bm + lrow + rr) * K + k0 + lc4];
            As[lc4 + 0][lrow + rr] = v.x;
            As[lc4 + 1][lrow + rr] = v.y;
            As[lc4 + 2][lrow + rr] = v.z;
            As[lc4 + 3][lrow + rr] = v.w;
        }
#pragma unroll
        for (int rr = 0; rr < GBN; rr += 64) {
            float4 v = *(const float4*)&Bw[(size_t)(bn + lrow + rr) * K + k0 + lc4];
            Bs[lc4 + 0][lrow + rr] = v.x;
            Bs[lc4 + 1][lrow + rr] = v.y;
            Bs[lc4 + 2][lrow + rr] = v.z;
            Bs[lc4 + 3][lrow + rr] = v.w;
        }
        __syncthreads();

#pragma unroll
        for (int kk = 0; kk < GBK; kk++) {
            float ra[8], rb[8];
            *(float4*)&ra[0] = *(const float4*)&As[kk][ty * 8];
            *(float4*)&ra[4] = *(const float4*)&As[kk][ty * 8 + 4];
            *(float4*)&rb[0] = *(const float4*)&Bs[kk][tx * 8];
            *(float4*)&rb[4] = *(const float4*)&Bs[kk][tx * 8 + 4];
#pragma unroll
            for (int i = 0; i < 8; i++)
#pragma unroll
                for (int j = 0; j < 8; j++) acc[i][j] += ra[i] * rb[j];
        }
        __syncthreads();
    }

    // epilogue
#pragma unroll
    for (int i = 0; i < 8; i++) {
        const int m = bm + ty * 8 + i;
#pragma unroll
        for (int j = 0; j < 8; j++) {
            const int n = bn + tx * 8 + j;
            const float val = acc[i][j] + bias[n];
            if (MODE == 0) {
                Cout[(size_t)m * N + n] = val;
            } else {
                // n = which*768 + h*64 + d ; m = b*T + t
                const int which = n / CC;
                const int rem = n - which * CC;
                const int h = rem >> 6;
                const int d = rem & 63;
                const int b = m / TT;
                const int t = m - b * TT;
                const size_t off = ((((size_t)which * BB + b) * HH + h) * TT + t) * DD + d;
                g_qkv[off] = val;
            }
        }
    }
}

// ---------------------------------------------------------------------------
// Flash attention: one thread per query row. Block = 64 threads (Br=64).
// grid.x = T/64 (q blocks), grid.y = B*H.
// heads 0..5: causal (k <= q); heads 6..11: anti-causal (k >= q).
// ---------------------------------------------------------------------------
#define ATBR 64
#define ATBC 32

__global__ __launch_bounds__(64)
void attn_kernel(const int* __restrict__ amask, float* __restrict__ ctx)
{
    const int qb = blockIdx.x;
    const int bh = blockIdx.y;
    const int b = bh / HH;
    const int h = bh % HH;
    const bool causal = (h < NLEFT);

    const size_t head_off = ((size_t)b * HH + h) * (size_t)TT * DD;
    const float* Qp = g_qkv + head_off;
    const float* Kp = g_qkv + (size_t)1 * BB * HH * TT * DD + head_off;
    const float* Vp = g_qkv + (size_t)2 * BB * HH * TT * DD + head_off;

    const int r = threadIdx.x;      // 0..63
    const int qr = qb * ATBR + r;   // global query row

    float q[DD];
#pragma unroll
    for (int i = 0; i < DD; i += 4) {
        float4 v = *(const float4*)&Qp[(size_t)qr * DD + i];
        q[i] = v.x; q[i + 1] = v.y; q[i + 2] = v.z; q[i + 3] = v.w;
    }

    float o[DD];
#pragma unroll
    for (int i = 0; i < DD; i++) o[i] = 0.f;
    float mrow = -1e30f;
    float lsum = 0.f;

    __shared__ float Ks[ATBC * DD];
    __shared__ float Vs[ATBC * DD];
    __shared__ int mk[ATBC];

    const int kt_beg = causal ? 0 : (qb * ATBR) / ATBC;                  // 2*qb
    const int kt_end = causal ? ((qb * ATBR + ATBR - 1) / ATBC + 1)      // 2*qb+2
                              : (TT / ATBC);

    for (int kt = kt_beg; kt < kt_end; kt++) {
        __syncthreads();
        // load K/V tile: 32 rows x 64 floats = 512 float4 each; 8 per thread
#pragma unroll
        for (int u = 0; u < 8; u++) {
            const int idx = u * 64 + r;       // 0..511
            const int row = idx >> 4;         // 16 float4 per row
            const int c4 = (idx & 15) * 4;
            *(float4*)&Ks[row * DD + c4] =
                *(const float4*)&Kp[((size_t)kt * ATBC + row) * DD + c4];
            *(float4*)&Vs[row * DD + c4] =
                *(const float4*)&Vp[((size_t)kt * ATBC + row) * DD + c4];
        }
        if (r < ATBC) mk[r] = amask[b * TT + kt * ATBC + r];
        __syncthreads();

        float s[ATBC];
        float tmax = -1e30f;
#pragma unroll 2
        for (int j = 0; j < ATBC; j++) {
            const int kcol = kt * ATBC + j;
            const float* kr = &Ks[j * DD];
            float s0 = 0.f, s1 = 0.f, s2 = 0.f, s3 = 0.f;
#pragma unroll
            for (int d = 0; d < DD; d += 4) {
                s0 += q[d] * kr[d];
                s1 += q[d + 1] * kr[d + 1];
                s2 += q[d + 2] * kr[d + 2];
                s3 += q[d + 3] * kr[d + 3];
            }
            float sv = ((s0 + s1) + (s2 + s3)) * 0.125f;
            const bool ok = (mk[j] != 0) && (causal ? (kcol <= qr) : (kcol >= qr));
            sv = ok ? sv : -1e30f;
            s[j] = sv;
            tmax = fmaxf(tmax, sv);
        }

        const float mnew = fmaxf(mrow, tmax);
        const float corr = __expf(mrow - mnew);
        lsum *= corr;
#pragma unroll
        for (int d = 0; d < DD; d++) o[d] *= corr;

#pragma unroll 2
        for (int j = 0; j < ATBC; j++) {
            const float p = __expf(s[j] - mnew);
            lsum += p;
            const float* vr = &Vs[j * DD];
#pragma unroll
            for (int d = 0; d < DD; d++) o[d] += p * vr[d];
        }
        mrow = mnew;
    }

    const float inv = 1.f / lsum;
    float* outp = ctx + ((size_t)b * TT + qr) * CC + h * DD;
#pragma unroll
    for (int d = 0; d < DD; d += 4) {
        float4 v;
        v.x = o[d] * inv; v.y = o[d + 1] * inv;
        v.z = o[d + 2] * inv; v.w = o[d + 3] * inv;
        *(float4*)&outp[d] = v;
    }
}

// ---------------------------------------------------------------------------
extern "C" void kernel_launch(void* const* d_in, const int* in_sizes, int n_in,
                              void* d_out, int out_size)
{
    const float* x       = (const float*)d_in[0];
    const int*   amask   = (const int*)d_in[1];
    const float* Wqkv_w  = (const float*)d_in[2];
    const float* Wqkv_b  = (const float*)d_in[3];
    const float* Wo_w    = (const float*)d_in[4];
    const float* Wo_b    = (const float*)d_in[5];
    float* out = (float*)d_out;

    float* d_ctx;
    cudaGetSymbolAddress((void**)&d_ctx, g_ctx);

    // 1) QKV projection: [4096,768] @ [2304,768]^T  -> scatter into g_qkv
    {
        dim3 grid(NQKV / GBN, MM / GBM);   // (18, 32)
        sgemm_nt_kernel<1><<<grid, 256>>>(x, Wqkv_w, Wqkv_b, nullptr,
                                          MM, NQKV, CC);
    }

    // 2) attention -> g_ctx [B,T,C]
    {
        dim3 grid(TT / ATBR, BB * HH);     // (32, 24)
        attn_kernel<<<grid, 64>>>(amask, d_ctx);
    }

    // 3) output projection: [4096,768] @ [768,768]^T + bias -> out
    {
        dim3 grid(CC / GBN, MM / GBM);     // (6, 32)
        sgemm_nt_kernel<0><<<grid, 256>>>(d_ctx, Wo_w, Wo_b, out,
                                          MM, CC, CC);
    }
}

// round 5
// speedup vs baseline: 4.1946x; 4.1946x over previous
#include <cuda_runtime.h>
#include <cuda_bf16.h>
#include <math.h>
#include <stdint.h>

#define BB 2
#define TT 2048
#define CC 768
#define HH 12
#define DD 64
#define NLEFT 6
#define NQKV (3 * CC)   // 2304
#define MM (BB * TT)    // 4096

// Scratch: qkv in [which][B][H][T][D] layout, ctx in [B][T][C]
__device__ float g_qkv[3ull * BB * HH * TT * DD];
__device__ float g_ctx[(size_t)BB * TT * CC];

// ---------------------------------------------------------------------------
// helpers
// ---------------------------------------------------------------------------
__device__ __forceinline__ float tf32r(float f) {
    uint32_t u;
    asm("cvt.rna.tf32.f32 %0, %1;" : "=r"(u) : "f"(f));
    return __uint_as_float(u);
}

__device__ __forceinline__ void mma_tf32(float* c, const uint32_t* a, const uint32_t* b) {
    asm("mma.sync.aligned.m16n8k8.row.col.f32.tf32.tf32.f32 "
        "{%0,%1,%2,%3}, {%4,%5,%6,%7}, {%8,%9}, {%0,%1,%2,%3};"
        : "+f"(c[0]), "+f"(c[1]), "+f"(c[2]), "+f"(c[3])
        : "r"(a[0]), "r"(a[1]), "r"(a[2]), "r"(a[3]), "r"(b[0]), "r"(b[1]));
}

// ---------------------------------------------------------------------------
// TF32 GEMM NT: C[m,n] = sum_k A[m,k]*Bw[n,k] + bias[n]
// 128x128 block, kblock 32, 256 threads (8 warps, 2x4), warp tile 64x32.
// smem stride 36 floats -> bank (4r+c)%32 conflict-free fragment loads.
// MODE 0: C to Cout[m*N+n].  MODE 1: scatter to g_qkv [which][B][H][T][D].
// ---------------------------------------------------------------------------
template <int MODE>
__global__ __launch_bounds__(256)
void gemm_tf32(const float* __restrict__ A, const float* __restrict__ Bw,
               const float* __restrict__ bias, float* __restrict__ Cout,
               int M, int N, int K)
{
    __shared__ float As[128 * 36];
    __shared__ float Bs[128 * 36];

    const int bm = blockIdx.y * 128;
    const int bn = blockIdx.x * 128;
    const int tid = threadIdx.x;
    const int lane = tid & 31;
    const int warp = tid >> 5;
    const int wm = (warp >> 2) * 64;
    const int wn = (warp & 3) * 32;

    float acc[4][4][4] = {};

    const int lrow = tid >> 3;          // 0..31
    const int lcol = (tid & 7) * 4;     // 0..28

    for (int k0 = 0; k0 < K; k0 += 32) {
        __syncthreads();
#pragma unroll
        for (int p = 0; p < 4; p++) {
            const int row = lrow + p * 32;
            float4 va = *(const float4*)&A[(size_t)(bm + row) * K + k0 + lcol];
            float4 vb = *(const float4*)&Bw[(size_t)(bn + row) * K + k0 + lcol];
            float* da = &As[row * 36 + lcol];
            da[0] = tf32r(va.x); da[1] = tf32r(va.y);
            da[2] = tf32r(va.z); da[3] = tf32r(va.w);
            float* db = &Bs[row * 36 + lcol];
            db[0] = tf32r(vb.x); db[1] = tf32r(vb.y);
            db[2] = tf32r(vb.z); db[3] = tf32r(vb.w);
        }
        __syncthreads();

#pragma unroll
        for (int ks = 0; ks < 4; ks++) {
            const int c0 = ks * 8 + (lane & 3);
            uint32_t af[4][4];
#pragma unroll
            for (int mi = 0; mi < 4; mi++) {
                const int r0 = wm + mi * 16 + (lane >> 2);
                af[mi][0] = __float_as_uint(As[r0 * 36 + c0]);
                af[mi][1] = __float_as_uint(As[(r0 + 8) * 36 + c0]);
                af[mi][2] = __float_as_uint(As[r0 * 36 + c0 + 4]);
                af[mi][3] = __float_as_uint(As[(r0 + 8) * 36 + c0 + 4]);
            }
#pragma unroll
            for (int nj = 0; nj < 4; nj++) {
                const int n0 = wn + nj * 8 + (lane >> 2);
                uint32_t bf[2];
                bf[0] = __float_as_uint(Bs[n0 * 36 + c0]);
                bf[1] = __float_as_uint(Bs[n0 * 36 + c0 + 4]);
#pragma unroll
                for (int mi = 0; mi < 4; mi++) mma_tf32(acc[mi][nj], af[mi], bf);
            }
        }
    }

    // epilogue
#pragma unroll
    for (int mi = 0; mi < 4; mi++) {
        const int r0 = bm + wm + mi * 16 + (lane >> 2);
#pragma unroll
        for (int nj = 0; nj < 4; nj++) {
            const int c = bn + wn + nj * 8 + 2 * (lane & 3);
            const float b0 = bias[c], b1 = bias[c + 1];
            float v00 = acc[mi][nj][0] + b0, v01 = acc[mi][nj][1] + b1;
            float v10 = acc[mi][nj][2] + b0, v11 = acc[mi][nj][3] + b1;
            if (MODE == 0) {
                *(float2*)&Cout[(size_t)r0 * N + c] = make_float2(v00, v01);
                *(float2*)&Cout[(size_t)(r0 + 8) * N + c] = make_float2(v10, v11);
            } else {
#pragma unroll
                for (int e = 0; e < 2; e++) {
                    const int n = c + e;
                    const int which = n / CC;
                    const int rem = n - which * CC;
                    const int hh = rem >> 6;
                    const int dd = rem & 63;
#pragma unroll
                    for (int rr = 0; rr < 2; rr++) {
                        const int m = r0 + rr * 8;
                        const int bb = m / TT;
                        const int t = m - bb * TT;
                        const size_t off =
                            ((((size_t)which * BB + bb) * HH + hh) * TT + t) * DD + dd;
                        g_qkv[off] = (rr == 0) ? (e == 0 ? v00 : v01)
                                               : (e == 0 ? v10 : v11);
                    }
                }
            }
        }
    }
}

// ---------------------------------------------------------------------------
// TF32 mma flash attention.
// Block: 128 threads (4 warps), handles one (b,h) and a 64-row q tile.
// Warp w owns q rows [q0 + 16w, q0 + 16w + 16). Bc = 64 keys per iter.
// Q fragments register-resident; P staged via smem (Q buffer reused).
// ---------------------------------------------------------------------------
#define QST 68   // Qs/Ps stride (bank map (4r+c)%32 conflict-free A-frags)
#define KST 68   // Ks stride   (B-frag same pattern)
#define VST 72   // Vs stride   (bank map (8k+d)%32 conflict-free B-frags)
#define ATTN_SMEM ((64*QST + 64*KST + 64*VST) * 4 + 64 * 4)

__global__ __launch_bounds__(128)
void attn_tf32(const int* __restrict__ amask, float* __restrict__ ctx)
{
    extern __shared__ float smf[];
    float* Qs = smf;               // 64 x QST, later reused as Ps
    float* Ks = smf + 64 * QST;
    float* Vs = Ks + 64 * KST;
    int* mks = (int*)(Vs + 64 * VST);

    const int qb = blockIdx.x;
    const int bh = blockIdx.y;
    const int b = bh / HH, h = bh % HH;
    const bool causal = (h < NLEFT);
    const int tid = threadIdx.x, lane = tid & 31, warp = tid >> 5;

    const size_t hoff = ((size_t)b * HH + h) * (size_t)TT * DD;
    const float* Qp = g_qkv + hoff;
    const float* Kp = g_qkv + (size_t)BB * HH * TT * DD + hoff;
    const float* Vp = g_qkv + 2ull * BB * HH * TT * DD + hoff;
    const int q0 = qb * 64;

    // stage Q tile (tf32-rounded)
#pragma unroll
    for (int u = 0; u < 8; u++) {
        const int linear = u * 128 + tid;
        const int row = linear >> 4, f4 = (linear & 15) * 4;
        float4 v = *(const float4*)&Qp[(size_t)(q0 + row) * DD + f4];
        float* d = &Qs[row * QST + f4];
        d[0] = tf32r(v.x); d[1] = tf32r(v.y); d[2] = tf32r(v.z); d[3] = tf32r(v.w);
    }
    __syncthreads();

    // Q fragments (8 k-steps over D=64)
    uint32_t qa[8][4];
    {
        const int r0 = warp * 16 + (lane >> 2);
#pragma unroll
        for (int kf = 0; kf < 8; kf++) {
            const int c0 = kf * 8 + (lane & 3);
            qa[kf][0] = __float_as_uint(Qs[r0 * QST + c0]);
            qa[kf][1] = __float_as_uint(Qs[(r0 + 8) * QST + c0]);
            qa[kf][2] = __float_as_uint(Qs[r0 * QST + c0 + 4]);
            qa[kf][3] = __float_as_uint(Qs[(r0 + 8) * QST + c0 + 4]);
        }
    }

    float oc[8][4] = {};
    float m0 = -1e30f, m1 = -1e30f, l0 = 0.f, l1 = 0.f;
    const int qrA = q0 + warp * 16 + (lane >> 2);
    const int qrB = qrA + 8;
    const int rps = warp * 16 + (lane >> 2);

    const int ktb = causal ? 0 : qb;
    const int kte = causal ? (qb + 1) : (TT / 64);

    for (int kt = ktb; kt < kte; kt++) {
        __syncthreads();
        // stage K/V tiles
#pragma unroll
        for (int u = 0; u < 8; u++) {
            const int linear = u * 128 + tid;
            const int row = linear >> 4, f4 = (linear & 15) * 4;
            float4 vk = *(const float4*)&Kp[(size_t)(kt * 64 + row) * DD + f4];
            float4 vv = *(const float4*)&Vp[(size_t)(kt * 64 + row) * DD + f4];
            float* dk = &Ks[row * KST + f4];
            dk[0] = tf32r(vk.x); dk[1] = tf32r(vk.y);
            dk[2] = tf32r(vk.z); dk[3] = tf32r(vk.w);
            float* dv = &Vs[row * VST + f4];
            dv[0] = tf32r(vv.x); dv[1] = tf32r(vv.y);
            dv[2] = tf32r(vv.z); dv[3] = tf32r(vv.w);
        }
        if (tid < 64) mks[tid] = amask[b * TT + kt * 64 + tid];
        __syncthreads();

        // S = Q K^T
        float sc[8][4] = {};
#pragma unroll
        for (int nj = 0; nj < 8; nj++) {
            const int n0 = nj * 8 + (lane >> 2);
#pragma unroll
            for (int kf = 0; kf < 8; kf++) {
                const int c0 = kf * 8 + (lane & 3);
                uint32_t bf[2];
                bf[0] = __float_as_uint(Ks[n0 * KST + c0]);
                bf[1] = __float_as_uint(Ks[n0 * KST + c0 + 4]);
                mma_tf32(sc[nj], qa[kf], bf);
            }
        }

        // scale + mask
        const bool diag = (kt == qb);
        float tmax0 = -1e30f, tmax1 = -1e30f;
#pragma unroll
        for (int nj = 0; nj < 8; nj++) {
            const int kl = nj * 8 + 2 * (lane & 3);
            const int key = kt * 64 + kl;
            const int mv0 = mks[kl], mv1 = mks[kl + 1];
            float s0 = sc[nj][0] * 0.125f, s1 = sc[nj][1] * 0.125f;
            float s2 = sc[nj][2] * 0.125f, s3 = sc[nj][3] * 0.125f;
            bool bd0A = (mv0 == 0), bd1A = (mv1 == 0);
            bool bd0B = bd0A, bd1B = bd1A;
            if (diag) {
                if (causal) {
                    bd0A |= (key > qrA); bd1A |= (key + 1 > qrA);
                    bd0B |= (key > qrB); bd1B |= (key + 1 > qrB);
                } else {
                    bd0A |= (key < qrA); bd1A |= (key + 1 < qrA);
                    bd0B |= (key < qrB); bd1B |= (key + 1 < qrB);
                }
            }
            s0 = bd0A ? -1e30f : s0; s1 = bd1A ? -1e30f : s1;
            s2 = bd0B ? -1e30f : s2; s3 = bd1B ? -1e30f : s3;
            sc[nj][0] = s0; sc[nj][1] = s1; sc[nj][2] = s2; sc[nj][3] = s3;
            tmax0 = fmaxf(tmax0, fmaxf(s0, s1));
            tmax1 = fmaxf(tmax1, fmaxf(s2, s3));
        }
        tmax0 = fmaxf(tmax0, __shfl_xor_sync(0xffffffffu, tmax0, 1));
        tmax0 = fmaxf(tmax0, __shfl_xor_sync(0xffffffffu, tmax0, 2));
        tmax1 = fmaxf(tmax1, __shfl_xor_sync(0xffffffffu, tmax1, 1));
        tmax1 = fmaxf(tmax1, __shfl_xor_sync(0xffffffffu, tmax1, 2));

        const float mn0 = fmaxf(m0, tmax0), mn1 = fmaxf(m1, tmax1);
        const float cr0 = __expf(m0 - mn0), cr1 = __expf(m1 - mn1);
        m0 = mn0; m1 = mn1;
        l0 *= cr0; l1 *= cr1;
#pragma unroll
        for (int nj = 0; nj < 8; nj++) {
            oc[nj][0] *= cr0; oc[nj][1] *= cr0;
            oc[nj][2] *= cr1; oc[nj][3] *= cr1;
        }

        // P = exp(S - m), store to Ps (= Qs buffer; warp-private rows)
#pragma unroll
        for (int nj = 0; nj < 8; nj++) {
            const int kl = nj * 8 + 2 * (lane & 3);
            float p0 = __expf(sc[nj][0] - mn0), p1 = __expf(sc[nj][1] - mn0);
            float p2 = __expf(sc[nj][2] - mn1), p3 = __expf(sc[nj][3] - mn1);
            l0 += p0 + p1; l1 += p2 + p3;
            *(float2*)&Qs[rps * QST + kl] = make_float2(tf32r(p0), tf32r(p1));
            *(float2*)&Qs[(rps + 8) * QST + kl] = make_float2(tf32r(p2), tf32r(p3));
        }
        __syncwarp();

        // O += P V
#pragma unroll
        for (int kf = 0; kf < 8; kf++) {
            const int c0 = kf * 8 + (lane & 3);
            uint32_t pa[4];
            pa[0] = __float_as_uint(Qs[rps * QST + c0]);
            pa[1] = __float_as_uint(Qs[(rps + 8) * QST + c0]);
            pa[2] = __float_as_uint(Qs[rps * QST + c0 + 4]);
            pa[3] = __float_as_uint(Qs[(rps + 8) * QST + c0 + 4]);
#pragma unroll
            for (int nj = 0; nj < 8; nj++) {
                const int n0 = nj * 8 + (lane >> 2);
                uint32_t vb[2];
                vb[0] = __float_as_uint(Vs[c0 * VST + n0]);
                vb[1] = __float_as_uint(Vs[(c0 + 4) * VST + n0]);
                mma_tf32(oc[nj], pa, vb);
            }
        }
    }

    l0 += __shfl_xor_sync(0xffffffffu, l0, 1);
    l0 += __shfl_xor_sync(0xffffffffu, l0, 2);
    l1 += __shfl_xor_sync(0xffffffffu, l1, 1);
    l1 += __shfl_xor_sync(0xffffffffu, l1, 2);
    const float i0 = 1.f / l0, i1 = 1.f / l1;

#pragma unroll
    for (int nj = 0; nj < 8; nj++) {
        const int d = nj * 8 + 2 * (lane & 3);
        *(float2*)&ctx[((size_t)b * TT + qrA) * CC + h * DD + d] =
            make_float2(oc[nj][0] * i0, oc[nj][1] * i0);
        *(float2*)&ctx[((size_t)b * TT + qrB) * CC + h * DD + d] =
            make_float2(oc[nj][2] * i1, oc[nj][3] * i1);
    }
}

// ---------------------------------------------------------------------------
extern "C" void kernel_launch(void* const* d_in, const int* in_sizes, int n_in,
                              void* d_out, int out_size)
{
    const float* x      = (const float*)d_in[0];
    const int*   amask  = (const int*)d_in[1];
    const float* Wqkv_w = (const float*)d_in[2];
    const float* Wqkv_b = (const float*)d_in[3];
    const float* Wo_w   = (const float*)d_in[4];
    const float* Wo_b   = (const float*)d_in[5];
    float* out = (float*)d_out;

    float* d_ctx;
    cudaGetSymbolAddress((void**)&d_ctx, g_ctx);

    cudaFuncSetAttribute(attn_tf32, cudaFuncAttributeMaxDynamicSharedMemorySize,
                         ATTN_SMEM);

    // 1) QKV projection -> g_qkv
    {
        dim3 grid(NQKV / 128, MM / 128);   // (18, 32)
        gemm_tf32<1><<<grid, 256>>>(x, Wqkv_w, Wqkv_b, nullptr, MM, NQKV, CC);
    }
    // 2) attention -> g_ctx
    {
        dim3 grid(TT / 64, BB * HH);       // (32, 24)
        attn_tf32<<<grid, 128, ATTN_SMEM>>>(amask, d_ctx);
    }
    // 3) output projection -> out
    {
        dim3 grid(CC / 128, MM / 128);     // (6, 32)
        gemm_tf32<0><<<grid, 256>>>(d_ctx, Wo_w, Wo_b, out, MM, CC, CC);
    }
}